// round 16
// baseline (speedup 1.0000x reference)
#include <cuda_runtime.h>
#include <cuda_fp16.h>

// CapsuleLayer dynamic routing, GB300 sm_103a.
// B=64, I=2048, Din=16, J=32, D=32, 3 routing iters.
//
// uhat2: grid (j=32, itile=16). Block streams its 128 i's through an 8-stage
// cp.async ring (stage = 2KB W[j,i,:,:] contiguous + 4KB x[:,i,:]), computes
// u_hat fp16 -> g_U[b][i][j*32+d] AND accumulates the iter-0 uniform-c sum s0
// in registers (single writer per (itile,b,j,d) -> deterministic), writing
// g_spart[itile] directly. DELETES the route0 streaming pass (256 MB).
// Round-16 fixes vs the correct-but-slow round-15: occ 2 (no spills) and
// bank-conflict-free LDS via k-rotation swizzles (W by q, x by b>>1).
// Routes + squash: round-13 proven, unchanged.

#define BB 64
#define II 2048
#define CC 16
#define JJ 32
#define DD 32
#define NTILE 16   // i-tiles
#define NSTAGE 5   // route ring stages (16KB each)
#define NITER 16   // route stages per block
#define NST 8      // uhat2 ring stages
#define STGB 6144  // uhat2 stage bytes: 2048 W + 4096 x
#define UITER 128  // uhat2 i per block

typedef unsigned long long u64;
typedef unsigned int u32;

__device__ __half g_U[(size_t)BB * II * JJ * DD];   // 256 MB scratch (fp16)
__device__ float g_osum[BB * JJ * DD];              // running output sum
__device__ float g_spart[NTILE][BB * JJ * DD];      // per-itile partial s

// ---------- packed fp32x2 helpers ----------
__device__ __forceinline__ u64 fma2(u64 a, u64 b, u64 c) {
    u64 d;
    asm("fma.rn.f32x2 %0, %1, %2, %3;" : "=l"(d) : "l"(a), "l"(b), "l"(c));
    return d;
}
__device__ __forceinline__ u64 add2(u64 a, u64 b) {
    u64 d;
    asm("add.rn.f32x2 %0, %1, %2;" : "=l"(d) : "l"(a), "l"(b));
    return d;
}
__device__ __forceinline__ float hsum2(u64 v) {
    float a, b;
    asm("mov.b64 {%0, %1}, %2;" : "=f"(a), "=f"(b) : "l"(v));
    return a + b;
}
// pack two fp32 -> fp16x2 (round-to-nearest; == __floats2half2_rn)
__device__ __forceinline__ u32 cvtpack(float lo, float hi) {
    u32 h;
    asm("cvt.rn.f16x2.f32 %0, %1, %2;" : "=r"(h) : "f"(hi), "f"(lo));
    return h;
}

// ---------- cp.async helpers ----------
__device__ __forceinline__ void cpasync16(unsigned smem_addr, const void* g) {
    asm volatile("cp.async.cg.shared.global [%0], [%1], 16;" ::"r"(smem_addr),
                 "l"(g));
}
__device__ __forceinline__ void cpcommit() {
    asm volatile("cp.async.commit_group;");
}
template <int N>
__device__ __forceinline__ void cpwait() {
    asm volatile("cp.async.wait_group %0;" ::"n"(N));
}

// ---------------------------------------------------------------------------
// Kernel A (uhat2): u_hat[b][i][j*32+d] = sum_c W[j][i][d][c] * x[b][i][c]
// (fp16), plus s0[b,j,d] = (1/32) sum_i u_hat (fp32 registers).
// Thread: b = w*8+(l&7), q = l>>3 -> rows q*8..q*8+7.
// LDS swizzles: W chunk (k+q)&3 (4 q's -> 4 distinct banks); x chunk
// (k + (b>>1))&3 (8 b's -> 8 distinct banks per half). Conflict-free.
// ---------------------------------------------------------------------------
__global__ void __launch_bounds__(256, 2)
uhat_kernel(const float* __restrict__ x, const float* __restrict__ W) {
    extern __shared__ __align__(16) char dsm[];
    const int j = blockIdx.x;      // 0..31
    const int itile = blockIdx.y;  // 0..15
    const int t = threadIdx.x;
    const int w = t >> 5, l = t & 31;
    const int b = w * 8 + (l & 7);
    const int q = l >> 3;
    const int i0 = itile * UITER;

    const char* Wg =
        reinterpret_cast<const char*>(W) + ((size_t)j * II + i0) * 2048;
    const char* Xg = reinterpret_cast<const char*>(x);
    const unsigned sb0 = (unsigned)__cvta_generic_to_shared(dsm);

    // copy roles: t<128 -> W granule t; t>=128 -> x granules g, g+1.
    const int xg = (t - 128) * 2;
    const int xb0 = xg >> 2, xp0 = xg & 3;
    const int xb1 = (xg + 1) >> 2, xp1 = (xg + 1) & 3;

    // prologue: stages 0..NST-2
    #pragma unroll
    for (int s = 0; s < NST - 1; s++) {
        unsigned sb = sb0 + (unsigned)(s * STGB);
        if (t < 128) {
            cpasync16(sb + (unsigned)(t * 16), Wg + (size_t)s * 2048 + t * 16);
        } else {
            cpasync16(sb + (unsigned)(2048 + xg * 16),
                      Xg + ((size_t)xb0 * II + i0 + s) * 64 + xp0 * 16);
            cpasync16(sb + (unsigned)(2048 + xg * 16 + 16),
                      Xg + ((size_t)xb1 * II + i0 + s) * 64 + xp1 * 16);
        }
        cpcommit();
    }

    float s0[8];
    #pragma unroll
    for (int dd = 0; dd < 8; dd++) s0[dd] = 0.f;

    // output base: byte = b*II*2048 + i*2048 + j*64 + q*16
    char* gu = reinterpret_cast<char*>(g_U) + (size_t)b * (II * 2048) +
               (size_t)i0 * 2048 + j * 64 + q * 16;

    const int xrot = (b >> 1) & 3;  // x bank-rotation
    int rd = 0, wr = NST - 1;
    for (int it = 0; it < UITER; it++) {
        cpwait<NST - 2>();  // stage rd resident
        __syncthreads();
        const char* sb = dsm + rd * STGB;

        // x[b][0:16] fp32, chunk order rotated by (b>>1) -> conflict-free
        u64 xr[8];
        {
            const float4* xp = reinterpret_cast<const float4*>(sb + 2048 + b * 64);
            #pragma unroll
            for (int k = 0; k < 4; k++) {
                int kk = (k + xrot) & 3;
                float4 f = xp[kk];
                const u64* pv = reinterpret_cast<const u64*>(&f);
                xr[2 * kk] = pv[0];
                xr[2 * kk + 1] = pv[1];
            }
        }
        float vv[8];
        #pragma unroll
        for (int dd = 0; dd < 8; dd++) {
            const float4* wp =
                reinterpret_cast<const float4*>(sb + (q * 8 + dd) * 64);
            u64 a0 = 0ULL, a1 = 0ULL;
            #pragma unroll
            for (int k = 0; k < 4; k++) {
                int kk = (k + q) & 3;  // 4 q's -> 4 distinct banks
                float4 f = wp[kk];
                const u64* pv = reinterpret_cast<const u64*>(&f);
                a0 = fma2(pv[0], xr[2 * kk], a0);
                a1 = fma2(pv[1], xr[2 * kk + 1], a1);
            }
            float v = hsum2(add2(a0, a1));
            s0[dd] += v;
            vv[dd] = v;
        }
        // pack 8 halves (d ascending) -> one STG.128 (64B/b, sector-aligned)
        uint4 o;
        o.x = cvtpack(vv[0], vv[1]);
        o.y = cvtpack(vv[2], vv[3]);
        o.z = cvtpack(vv[4], vv[5]);
        o.w = cvtpack(vv[6], vv[7]);
        *reinterpret_cast<uint4*>(gu + (size_t)it * 2048) = o;

        // refill slot wr; commit EVERY iteration (empty tail) for alignment
        {
            int s = it + NST - 1;
            if (s < UITER) {
                unsigned sb2 = sb0 + (unsigned)(wr * STGB);
                if (t < 128) {
                    cpasync16(sb2 + (unsigned)(t * 16),
                              Wg + (size_t)s * 2048 + t * 16);
                } else {
                    cpasync16(sb2 + (unsigned)(2048 + xg * 16),
                              Xg + ((size_t)xb0 * II + i0 + s) * 64 + xp0 * 16);
                    cpasync16(sb2 + (unsigned)(2048 + xg * 16 + 16),
                              Xg + ((size_t)xb1 * II + i0 + s) * 64 + xp1 * 16);
                }
            }
            cpcommit();
        }
        if (++rd == NST) rd = 0;
        if (++wr == NST) wr = 0;
    }

    // s0 partial for this itile (single writer per element -> deterministic)
    #pragma unroll
    for (int dd = 0; dd < 8; dd++)
        g_spart[itile][b * (JJ * DD) + j * DD + q * 8 + dd] = s0[dd] * 0.03125f;
}

// ---------------------------------------------------------------------------
// Route compute step: lane l chunk m (uint4 = 8 halfs) holds j = 8m + (l>>2),
// d-seg (l&3)*8..+7. (Round-13 proven, unchanged.)
// ---------------------------------------------------------------------------
__device__ __forceinline__ void cvt8(const uint4& r, float* uf) {
    const __half2* h = reinterpret_cast<const __half2*>(&r);
    #pragma unroll
    for (int p = 0; p < 4; p++) {
        float2 f = __half22float2(h[p]);
        uf[2 * p] = f.x;
        uf[2 * p + 1] = f.y;
    }
}

__device__ __forceinline__ void route_step(const uint4* r, const float ov[4][8],
                                           float sacc[4][8]) {
    float uf[4][8];
    #pragma unroll
    for (int m = 0; m < 4; m++) cvt8(r[m], uf[m]);
    float tp[4];
    #pragma unroll
    for (int m = 0; m < 4; m++) {
        float a = uf[m][0] * ov[m][0];
        #pragma unroll
        for (int k = 1; k < 8; k++) a = fmaf(uf[m][k], ov[m][k], a);
        tp[m] = a;
    }
    #pragma unroll
    for (int s = 1; s < 4; s <<= 1)
        #pragma unroll
        for (int m = 0; m < 4; m++)
            tp[m] += __shfl_xor_sync(0xffffffffu, tp[m], s);
    float e[4], ss = 0.f;
    #pragma unroll
    for (int m = 0; m < 4; m++) {
        e[m] = __expf(tp[m]);
        ss += e[m];
    }
    ss += __shfl_xor_sync(0xffffffffu, ss, 4);
    ss += __shfl_xor_sync(0xffffffffu, ss, 8);
    ss += __shfl_xor_sync(0xffffffffu, ss, 16);
    float inv = __fdividef(1.0f, ss);
    float c[4];
    #pragma unroll
    for (int m = 0; m < 4; m++) c[m] = e[m] * inv;
    #pragma unroll
    for (int m = 0; m < 4; m++)
        #pragma unroll
        for (int k = 0; k < 8; k++) sacc[m][k] = fmaf(c[m], uf[m][k], sacc[m][k]);
}

// ---------------------------------------------------------------------------
// Kernel B: softmax routing pass, 5-stage block-wide cp.async ring, one
// barrier per iteration. (Round-13 proven, unchanged.)
// ---------------------------------------------------------------------------
template <int DIR>
__global__ void __launch_bounds__(256, 2) route_kernel() {
    extern __shared__ __align__(16) char dsm[];
    __half* sU = reinterpret_cast<__half*>(dsm);                  // NSTAGE*16KB
    float* sS = reinterpret_cast<float*>(dsm + NSTAGE * 16384);   // 8*1024 f

    const int itile = DIR ? (NTILE - 1 - (int)blockIdx.x) : (int)blockIdx.x;
    const int b = DIR ? (BB - 1 - (int)blockIdx.y) : (int)blockIdx.y;
    const int t = threadIdx.x, w = t >> 5, l = t & 31;

    float ov[4][8];
    {
        const float4* op = reinterpret_cast<const float4*>(g_osum + b * (JJ * DD));
        #pragma unroll
        for (int m = 0; m < 4; m++) {
            float4 f0 = op[m * 64 + 2 * l], f1 = op[m * 64 + 2 * l + 1];
            ov[m][0] = f0.x; ov[m][1] = f0.y; ov[m][2] = f0.z; ov[m][3] = f0.w;
            ov[m][4] = f1.x; ov[m][5] = f1.y; ov[m][6] = f1.z; ov[m][7] = f1.w;
        }
    }
    float sacc[4][8];
    #pragma unroll
    for (int m = 0; m < 4; m++)
        #pragma unroll
        for (int k = 0; k < 8; k++) sacc[m][k] = 0.f;

    const char* gbt = reinterpret_cast<const char*>(g_U) +
                      ((size_t)b * II + itile * 128) * 2048 + (size_t)t * 16;
    const unsigned su_base =
        (unsigned)__cvta_generic_to_shared(sU) + (unsigned)(t * 16);

    #pragma unroll
    for (int s = 0; s < NSTAGE - 1; s++) {
        #pragma unroll
        for (int k = 0; k < 4; k++)
            cpasync16(su_base + (unsigned)(s * 16384 + k * 4096),
                      gbt + (size_t)s * 16384 + k * 4096);
        cpcommit();
    }

    int rd = 0;
    int wr = NSTAGE - 1;
    for (int it = 0; it < NITER; it++) {
        cpwait<NSTAGE - 2>();
        __syncthreads();
        const uint4* p =
            reinterpret_cast<const uint4*>(sU + rd * 8192 + w * 1024);
        uint4 r[4];
        #pragma unroll
        for (int m = 0; m < 4; m++) r[m] = p[m * 32 + l];
        route_step(r, ov, sacc);
        {
            int s = it + NSTAGE - 1;
            if (s < NITER) {
                #pragma unroll
                for (int k = 0; k < 4; k++)
                    cpasync16(su_base + (unsigned)(wr * 16384 + k * 4096),
                              gbt + (size_t)s * 16384 + k * 4096);
            }
            cpcommit();
        }
        if (++rd == NSTAGE) rd = 0;
        if (++wr == NSTAGE) wr = 0;
    }
    __syncthreads();

    float4* sp = reinterpret_cast<float4*>(sS + w * 1024);
    #pragma unroll
    for (int m = 0; m < 4; m++) {
        sp[(m * 32 + l) * 2 + 0] =
            make_float4(sacc[m][0], sacc[m][1], sacc[m][2], sacc[m][3]);
        sp[(m * 32 + l) * 2 + 1] =
            make_float4(sacc[m][4], sacc[m][5], sacc[m][6], sacc[m][7]);
    }
    __syncthreads();
    for (int idx = t; idx < JJ * DD; idx += 256) {
        float v = 0.f;
        #pragma unroll
        for (int ww = 0; ww < 8; ww++) v += sS[ww * 1024 + idx];
        g_spart[itile][b * (JJ * DD) + idx] = v;
    }
}

// ---------------------------------------------------------------------------
// Kernel C: reduce itile partials, squash, update osum / write final out.
// mode 0: osum = o ; mode 1: osum += o ; mode 2: out = o.
// ---------------------------------------------------------------------------
__global__ void __launch_bounds__(256) squash_kernel(float* __restrict__ out,
                                                     int mode) {
    const int t = threadIdx.x;
    const int bj = blockIdx.x * 8 + (t >> 5);
    const int l = t & 31;
    float v = 0.f;
    #pragma unroll
    for (int it = 0; it < NTILE; it++) v += g_spart[it][bj * DD + l];
    float s2 = v * v;
    #pragma unroll
    for (int s = 1; s < 32; s <<= 1) s2 += __shfl_xor_sync(0xffffffffu, s2, s);
    float scale = (s2 / (1.0f + s2)) * rsqrtf(s2 + 1e-7f);
    float o = scale * v;
    if (mode == 2)
        out[bj * DD + l] = o;
    else if (mode == 1)
        g_osum[bj * DD + l] += o;
    else
        g_osum[bj * DD + l] = o;
}

// ---------------------------------------------------------------------------
extern "C" void kernel_launch(void* const* d_in, const int* in_sizes, int n_in,
                              void* d_out, int out_size) {
    const float* x;
    const float* W;
    if (in_sizes[0] == BB * II * CC) {
        x = (const float*)d_in[0];
        W = (const float*)d_in[1];
    } else {
        x = (const float*)d_in[1];
        W = (const float*)d_in[0];
    }

    const int uhat_smem = NST * STGB;                                      // 49152
    const int route_smem = NSTAGE * 16384 + 8 * 1024 * (int)sizeof(float); // 114688
    cudaFuncSetAttribute(uhat_kernel, cudaFuncAttributeMaxDynamicSharedMemorySize,
                         uhat_smem);
    cudaFuncSetAttribute(route_kernel<0>,
                         cudaFuncAttributeMaxDynamicSharedMemorySize, route_smem);
    cudaFuncSetAttribute(route_kernel<1>,
                         cudaFuncAttributeMaxDynamicSharedMemorySize, route_smem);

    float* out = (float*)d_out;
    uhat_kernel<<<dim3(JJ, NTILE), 256, uhat_smem>>>(x, W);
    squash_kernel<<<BB * JJ / 8, 256>>>(out, 0);
    route_kernel<0><<<dim3(NTILE, BB), 256, route_smem>>>();
    squash_kernel<<<BB * JJ / 8, 256>>>(out, 1);
    route_kernel<1><<<dim3(NTILE, BB), 256, route_smem>>>();
    squash_kernel<<<BB * JJ / 8, 256>>>(out, 2);
}

// round 17
// speedup vs baseline: 1.9155x; 1.9155x over previous
#include <cuda_runtime.h>
#include <cuda_fp16.h>

// CapsuleLayer dynamic routing, GB300 sm_103a.
// B=64, I=2048, Din=16, J=32, D=32, 3 routing iters.
//
// Round-13 proven structure (270.8us) with ONE change: uhat's j-loop is
// software-pipelined (W LDS for j+1 prefetched into a second register set
// while j is computed) to hide the 29-cyc LDS latency under the fma2 chain.
// Everything else verbatim: 5-stage block-wide cp.async route rings (one
// barrier/iter, commit-every-iter tail), separate squash kernels.

#define BB 64
#define II 2048
#define CC 16
#define JJ 32
#define DD 32
#define NTILE 16   // i-tiles (blocks) per b; block covers 128 i
#define NSTAGE 5   // cp.async ring stages (8 i = 16KB per stage)
#define NITER 16   // stages per block (128 i / 8)

typedef unsigned long long u64;

__device__ __half g_U[(size_t)BB * II * JJ * DD];   // 256 MB scratch (fp16)
__device__ float g_osum[BB * JJ * DD];              // running output sum
__device__ float g_spart[NTILE][BB * JJ * DD];      // per-itile partial s

// ---------- packed fp32x2 helpers ----------
__device__ __forceinline__ u64 fma2(u64 a, u64 b, u64 c) {
    u64 d;
    asm("fma.rn.f32x2 %0, %1, %2, %3;" : "=l"(d) : "l"(a), "l"(b), "l"(c));
    return d;
}
__device__ __forceinline__ u64 add2(u64 a, u64 b) {
    u64 d;
    asm("add.rn.f32x2 %0, %1, %2;" : "=l"(d) : "l"(a), "l"(b));
    return d;
}
__device__ __forceinline__ float hsum2(u64 v) {
    float a, b;
    asm("mov.b64 {%0, %1}, %2;" : "=f"(a), "=f"(b) : "l"(v));
    return a + b;
}

// ---------- cp.async helpers ----------
__device__ __forceinline__ void cpasync16(unsigned smem_addr, const void* g) {
    asm volatile("cp.async.cg.shared.global [%0], [%1], 16;" ::"r"(smem_addr),
                 "l"(g));
}
__device__ __forceinline__ void cpcommit() {
    asm volatile("cp.async.commit_group;");
}
template <int N>
__device__ __forceinline__ void cpwait() {
    asm volatile("cp.async.wait_group %0;" ::"n"(N));
}

// ---------------------------------------------------------------------------
// Kernel A: u_hat[b][i][j][d] = sum_c W[j][i][d][c] * x[b][i][c], fp16.
// One block per i. W chunk-major in smem (8 contiguous LDS.128 per (j,thread),
// conflict-free). Thread (bg = t>>4, q = t&15): 4 batches, d = 2q, 2q+1.
// j-loop software-pipelined: W regs for j+1 loaded before computing j.
// ---------------------------------------------------------------------------
__global__ void __launch_bounds__(256, 2)
uhat_kernel(const float* __restrict__ x, const float* __restrict__ W) {
    extern __shared__ __align__(16) char smraw[];
    float2* sW = reinterpret_cast<float2*>(smraw);        // [8][1024] = 64KB
    float* sX = reinterpret_cast<float*>(smraw + 65536);  // [64][16]  = 4KB
    const int i = blockIdx.x;
    const int t = threadIdx.x;

    const float4* Wg = reinterpret_cast<const float4*>(W);
    #pragma unroll
    for (int k = 0; k < 16; k++) {
        int v = t + 256 * k;
        int row = v >> 2, ch = v & 3;  // row = j*32 + d
        int j = row >> 5, d = row & 31;
        float4 f = Wg[(size_t)(j * II + i) * 128 + d * 4 + ch];
        sW[(2 * ch) * 1024 + row] = make_float2(f.x, f.y);
        sW[(2 * ch + 1) * 1024 + row] = make_float2(f.z, f.w);
    }
    {
        int b = t >> 2, r = t & 3;
        reinterpret_cast<float4*>(sX)[t] =
            reinterpret_cast<const float4*>(x)[(size_t)(b * II + i) * 4 + r];
    }
    __syncthreads();

    const int bg = t >> 4, q = t & 15;
    u64 xr[4][8];
    #pragma unroll
    for (int s = 0; s < 4; s++) {
        const u64* xp = reinterpret_cast<const u64*>(sX + (bg + 16 * s) * CC);
        #pragma unroll
        for (int k = 0; k < 8; k++) xr[s][k] = xp[k];
    }

    __half2* Uo = reinterpret_cast<__half2*>(g_U);
    const float4* sW4 = reinterpret_cast<const float4*>(sW);

    // prefetch W regs for j = 0
    u64 w0[8], w1[8];
    #pragma unroll
    for (int k = 0; k < 8; k++) {
        float4 wv = sW4[k * 512 + 0 * 16 + q];
        const u64* pv = reinterpret_cast<const u64*>(&wv);
        w0[k] = pv[0];
        w1[k] = pv[1];
    }

    for (int j = 0; j < JJ; j++) {
        // prefetch j+1 while computing j (hides LDS latency under fma2 chain)
        u64 n0[8], n1[8];
        if (j + 1 < JJ) {
            #pragma unroll
            for (int k = 0; k < 8; k++) {
                float4 wv = sW4[k * 512 + (j + 1) * 16 + q];
                const u64* pv = reinterpret_cast<const u64*>(&wv);
                n0[k] = pv[0];
                n1[k] = pv[1];
            }
        }
        #pragma unroll
        for (int s = 0; s < 4; s++) {
            u64 a0 = 0ULL, a1 = 0ULL, b0 = 0ULL, b1 = 0ULL;
            #pragma unroll
            for (int k = 0; k < 8; k += 2) {
                a0 = fma2(w0[k],     xr[s][k],     a0);
                a1 = fma2(w0[k + 1], xr[s][k + 1], a1);
                b0 = fma2(w1[k],     xr[s][k],     b0);
                b1 = fma2(w1[k + 1], xr[s][k + 1], b1);
            }
            float d0 = hsum2(add2(a0, a1));
            float d1 = hsum2(add2(b0, b1));
            int b = bg + 16 * s;
            Uo[(size_t)(b * II + i) * 512 + j * 16 + q] = __floats2half2_rn(d0, d1);
        }
        if (j + 1 < JJ) {
            #pragma unroll
            for (int k = 0; k < 8; k++) {
                w0[k] = n0[k];
                w1[k] = n1[k];
            }
        }
    }
}

// ---------------------------------------------------------------------------
// Route compute step: lane l chunk m (uint4 = 8 halfs) holds j = 8m + (l>>2),
// d-seg (l&3)*8..+7. Logit reduce over 4-lane groups; softmax over 32 j via
// in-thread + xor 4,8,16.
// ---------------------------------------------------------------------------
__device__ __forceinline__ void cvt8(const uint4& r, float* uf) {
    const __half2* h = reinterpret_cast<const __half2*>(&r);
    #pragma unroll
    for (int p = 0; p < 4; p++) {
        float2 f = __half22float2(h[p]);
        uf[2 * p] = f.x;
        uf[2 * p + 1] = f.y;
    }
}

template <int MODE>
__device__ __forceinline__ void route_step(const uint4* r, const float ov[4][8],
                                           float sacc[4][8]) {
    float uf[4][8];
    #pragma unroll
    for (int m = 0; m < 4; m++) cvt8(r[m], uf[m]);
    float c[4];
    if (MODE == 0) {
        #pragma unroll
        for (int m = 0; m < 4; m++) c[m] = 0.03125f;
    } else {
        float tp[4];
        #pragma unroll
        for (int m = 0; m < 4; m++) {
            float a = uf[m][0] * ov[m][0];
            #pragma unroll
            for (int k = 1; k < 8; k++) a = fmaf(uf[m][k], ov[m][k], a);
            tp[m] = a;
        }
        #pragma unroll
        for (int s = 1; s < 4; s <<= 1)
            #pragma unroll
            for (int m = 0; m < 4; m++)
                tp[m] += __shfl_xor_sync(0xffffffffu, tp[m], s);
        float e[4], ss = 0.f;
        #pragma unroll
        for (int m = 0; m < 4; m++) {
            e[m] = __expf(tp[m]);
            ss += e[m];
        }
        ss += __shfl_xor_sync(0xffffffffu, ss, 4);
        ss += __shfl_xor_sync(0xffffffffu, ss, 8);
        ss += __shfl_xor_sync(0xffffffffu, ss, 16);
        float inv = __fdividef(1.0f, ss);
        #pragma unroll
        for (int m = 0; m < 4; m++) c[m] = e[m] * inv;
    }
    #pragma unroll
    for (int m = 0; m < 4; m++)
        #pragma unroll
        for (int k = 0; k < 8; k++) sacc[m][k] = fmaf(c[m], uf[m][k], sacc[m][k]);
}

// ---------------------------------------------------------------------------
// Kernel B: one routing pass with a 5-stage block-wide cp.async pipeline,
// ONE barrier per iteration (round-13 proven).
// ---------------------------------------------------------------------------
template <int MODE, int DIR>
__global__ void __launch_bounds__(256, 2) route_kernel() {
    extern __shared__ __align__(16) char dsm[];
    __half* sU = reinterpret_cast<__half*>(dsm);                  // NSTAGE*16KB
    float* sS = reinterpret_cast<float*>(dsm + NSTAGE * 16384);   // 8*1024 f

    const int itile = DIR ? (NTILE - 1 - (int)blockIdx.x) : (int)blockIdx.x;
    const int b = DIR ? (BB - 1 - (int)blockIdx.y) : (int)blockIdx.y;
    const int t = threadIdx.x, w = t >> 5, l = t & 31;

    float ov[4][8];
    if (MODE > 0) {
        const float4* op = reinterpret_cast<const float4*>(g_osum + b * (JJ * DD));
        #pragma unroll
        for (int m = 0; m < 4; m++) {
            float4 f0 = op[m * 64 + 2 * l], f1 = op[m * 64 + 2 * l + 1];
            ov[m][0] = f0.x; ov[m][1] = f0.y; ov[m][2] = f0.z; ov[m][3] = f0.w;
            ov[m][4] = f1.x; ov[m][5] = f1.y; ov[m][6] = f1.z; ov[m][7] = f1.w;
        }
    }
    float sacc[4][8];
    #pragma unroll
    for (int m = 0; m < 4; m++)
        #pragma unroll
        for (int k = 0; k < 8; k++) sacc[m][k] = 0.f;

    const char* gbt = reinterpret_cast<const char*>(g_U) +
                      ((size_t)b * II + itile * 128) * 2048 + (size_t)t * 16;
    const unsigned su_base =
        (unsigned)__cvta_generic_to_shared(sU) + (unsigned)(t * 16);

    #pragma unroll
    for (int s = 0; s < NSTAGE - 1; s++) {
        #pragma unroll
        for (int k = 0; k < 4; k++)
            cpasync16(su_base + (unsigned)(s * 16384 + k * 4096),
                      gbt + (size_t)s * 16384 + k * 4096);
        cpcommit();
    }

    int rd = 0;
    int wr = NSTAGE - 1;
    for (int it = 0; it < NITER; it++) {
        cpwait<NSTAGE - 2>();  // own copies for stage rd complete
        __syncthreads();       // all threads' copies complete; orders slot reuse
        const uint4* p =
            reinterpret_cast<const uint4*>(sU + rd * 8192 + w * 1024);
        uint4 r[4];
        #pragma unroll
        for (int m = 0; m < 4; m++) r[m] = p[m * 32 + l];
        route_step<MODE>(r, ov, sacc);
        {
            int s = it + NSTAGE - 1;
            if (s < NITER) {
                #pragma unroll
                for (int k = 0; k < 4; k++)
                    cpasync16(su_base + (unsigned)(wr * 16384 + k * 4096),
                              gbt + (size_t)s * 16384 + k * 4096);
            }
            cpcommit();
        }
        if (++rd == NSTAGE) rd = 0;
        if (++wr == NSTAGE) wr = 0;
    }
    __syncthreads();  // all consumption done before sS write-out below

    float4* sp = reinterpret_cast<float4*>(sS + w * 1024);
    #pragma unroll
    for (int m = 0; m < 4; m++) {
        sp[(m * 32 + l) * 2 + 0] =
            make_float4(sacc[m][0], sacc[m][1], sacc[m][2], sacc[m][3]);
        sp[(m * 32 + l) * 2 + 1] =
            make_float4(sacc[m][4], sacc[m][5], sacc[m][6], sacc[m][7]);
    }
    __syncthreads();
    for (int idx = t; idx < JJ * DD; idx += 256) {
        float v = 0.f;
        #pragma unroll
        for (int ww = 0; ww < 8; ww++) v += sS[ww * 1024 + idx];
        g_spart[itile][b * (JJ * DD) + idx] = v;
    }
}

// ---------------------------------------------------------------------------
// Kernel C: reduce itile partials, squash, update osum / write final out.
// mode 0: osum = o ; mode 1: osum += o ; mode 2: out = o.
// ---------------------------------------------------------------------------
__global__ void __launch_bounds__(256) squash_kernel(float* __restrict__ out,
                                                     int mode) {
    const int t = threadIdx.x;
    const int bj = blockIdx.x * 8 + (t >> 5);
    const int l = t & 31;
    float v = 0.f;
    #pragma unroll
    for (int it = 0; it < NTILE; it++) v += g_spart[it][bj * DD + l];
    float s2 = v * v;
    #pragma unroll
    for (int s = 1; s < 32; s <<= 1) s2 += __shfl_xor_sync(0xffffffffu, s2, s);
    float scale = (s2 / (1.0f + s2)) * rsqrtf(s2 + 1e-7f);
    float o = scale * v;
    if (mode == 2)
        out[bj * DD + l] = o;
    else if (mode == 1)
        g_osum[bj * DD + l] += o;
    else
        g_osum[bj * DD + l] = o;
}

// ---------------------------------------------------------------------------
extern "C" void kernel_launch(void* const* d_in, const int* in_sizes, int n_in,
                              void* d_out, int out_size) {
    const float* x;
    const float* W;
    if (in_sizes[0] == BB * II * CC) {
        x = (const float*)d_in[0];
        W = (const float*)d_in[1];
    } else {
        x = (const float*)d_in[1];
        W = (const float*)d_in[0];
    }

    const int uhat_smem = 65536 + BB * CC * (int)sizeof(float);            // 69632
    const int route_smem = NSTAGE * 16384 + 8 * 1024 * (int)sizeof(float); // 114688
    cudaFuncSetAttribute(uhat_kernel, cudaFuncAttributeMaxDynamicSharedMemorySize,
                         uhat_smem);
    cudaFuncSetAttribute(route_kernel<0, 1>,
                         cudaFuncAttributeMaxDynamicSharedMemorySize, route_smem);
    cudaFuncSetAttribute(route_kernel<1, 0>,
                         cudaFuncAttributeMaxDynamicSharedMemorySize, route_smem);
    cudaFuncSetAttribute(route_kernel<2, 1>,
                         cudaFuncAttributeMaxDynamicSharedMemorySize, route_smem);

    float* out = (float*)d_out;
    uhat_kernel<<<II, 256, uhat_smem>>>(x, W);
    route_kernel<0, 1><<<dim3(NTILE, BB), 256, route_smem>>>();
    squash_kernel<<<BB * JJ / 8, 256>>>(out, 0);
    route_kernel<1, 0><<<dim3(NTILE, BB), 256, route_smem>>>();
    squash_kernel<<<BB * JJ / 8, 256>>>(out, 1);
    route_kernel<2, 1><<<dim3(NTILE, BB), 256, route_smem>>>();
    squash_kernel<<<BB * JJ / 8, 256>>>(out, 2);
}